// round 3
// baseline (speedup 1.0000x reference)
#include <cuda_runtime.h>

#define NA 96
#define NB 96
#define NS 64
#define QPB 8            // queries per block, one warp each
#define NTHREADS (QPB * 32)
#define W 7              // folded numerator window (radius 3)
#define NTRIP (W * W * W)   // 343
#define NITER ((NTRIP + 31) / 32)  // 11

__global__ __launch_bounds__(NTHREADS)
void latent_lookup_kernel(const float* __restrict__ q,
                          const float* __restrict__ rel,
                          const float* __restrict__ origin,
                          const float* __restrict__ spacing,
                          const float* __restrict__ temp,
                          float* __restrict__ out, int batch) {
    const int warp = threadIdx.x >> 5;
    const int lane = threadIdx.x & 31;
    const int b = blockIdx.x * QPB + warp;
    if (b >= batch) return;

    __shared__ float s_raw[QPB][3][15];
    __shared__ float s_fold[QPB][3][W];

    // ---- broadcast loads of query + params ----
    const float q0 = __ldg(&q[b * 3 + 0]);
    const float q1 = __ldg(&q[b * 3 + 1]);
    const float q2 = __ldg(&q[b * 3 + 2]);
    const float o0 = __ldg(&origin[0]), o1 = __ldg(&origin[1]), o2 = __ldg(&origin[2]);
    const float s0 = __ldg(&spacing[0]), s1 = __ldg(&spacing[1]), s2 = __ldg(&spacing[2]);
    const float inv_t = 1.0f / (__ldg(&temp[0]) + 1e-8f);

    // ---- per-thread voxel (round-half-even matches jnp.round) ----
    const int v0 = min(max((int)rintf((q0 - o0) / s0), 1), NA - 2);
    const int v1 = min(max((int)rintf((q1 - o1) / s1), 1), NB - 2);
    const int v2 = min(max((int)rintf((q2 - o2) / s2), 1), NS - 2);

    // ---- issue all gather loads first (addresses need only vox) ----
    float m[NITER];
    unsigned ii[NITER], jj[NITER], kk[NITER];
    #pragma unroll
    for (int u = 0; u < NITER; u++) {
        unsigned f = lane + 32u * u;
        if (f < NTRIP) {
            unsigned i = f / 49u;
            unsigned r = f - 49u * i;
            unsigned j = r / 7u;
            unsigned k = r - 7u * j;
            ii[u] = i; jj[u] = j; kk[u] = k;
            int cx = min(max(v0 + (int)i - 3, 0), NA - 1);
            int cy = min(max(v1 + (int)j - 3, 0), NB - 1);
            int cz = min(max(v2 + (int)k - 3, 0), NS - 1);
            m[u] = __ldg(&rel[cx * (NB * NS) + cy * NS + cz]);
        }
    }

    // ---- raw 15-entry per-axis weight tables (overlaps load latency) ----
    if (lane < 15) {
        int o = lane;
        int cx = min(max(v0 + o - 7, 0), NA - 1);
        int cy = min(max(v1 + o - 7, 0), NB - 1);
        int cz = min(max(v2 + o - 7, 0), NS - 1);
        float dx = q0 - (float)cx;
        float dy = q1 - (float)cy;
        float dz = q2 - (float)cz;
        s_raw[warp][0][o] = __expf(-dx * dx * inv_t);
        s_raw[warp][1][o] = __expf(-dy * dy * inv_t);
        s_raw[warp][2][o] = __expf(-dz * dz * inv_t);
    }

    // ---- hard path on lane 31 (fully overlapped) ----
    if (lane == 31) {
        float qn = __fadd_rn(__fadd_rn(__fmul_rn(q0, q0), __fmul_rn(q1, q1)),
                             __fmul_rn(q2, q2));
        int f0 = (int)floorf(q0);
        int f1 = (int)floorf(q1);
        int f2 = (int)floorf(q2);
        float best = 3.4e38f;
        int bestIdx = 0x7fffffff;
        #pragma unroll
        for (int a0 = 0; a0 < 2; a0++)
            #pragma unroll
            for (int a1 = 0; a1 < 2; a1++)
                #pragma unroll
                for (int a2 = 0; a2 < 2; a2++) {
                    int c0 = min(max(f0 + a0, 0), NA - 1);
                    int c1 = min(max(f1 + a1, 0), NB - 1);
                    int c2 = min(max(f2 + a2, 0), NS - 1);
                    float in_ = (float)(c0 * c0 + c1 * c1 + c2 * c2);
                    float dot = __fmaf_rn(q2, (float)c2,
                                 __fmaf_rn(q1, (float)c1,
                                  __fmul_rn(q0, (float)c0)));
                    float d = __fsub_rn(__fadd_rn(qn, in_), __fmul_rn(2.0f, dot));
                    int flat = (c0 * NB + c1) * NS + c2;
                    if (d < best || (d == best && flat < bestIdx)) {
                        best = d; bestIdx = flat;
                    }
                }
        out[b] = __ldg(&rel[bestIdx]);
    }

    __syncwarp();

    // ---- fold tail offsets into window edge slots ----
    // slot s (0..6) <- raw offset s+4; s==0 also sums raw 0..3, s==6 raw 11..14.
    // Per-axis sum is preserved exactly -> denominator exact.
    if (lane < 21) {
        int a = lane / 7;
        int s = lane - a * 7;
        float w = s_raw[warp][a][s + 4];
        if (s == 0)
            w += s_raw[warp][a][0] + s_raw[warp][a][1] +
                 s_raw[warp][a][2] + s_raw[warp][a][3];
        if (s == 6)
            w += s_raw[warp][a][11] + s_raw[warp][a][12] +
                 s_raw[warp][a][13] + s_raw[warp][a][14];
        s_fold[warp][a][s] = w;
    }
    __syncwarp();

    // ---- exact denominator: product of full per-axis sums ----
    float sx = 0.0f, sy = 0.0f, sz = 0.0f;
    #pragma unroll
    for (int s = 0; s < W; s++) {
        sx += s_fold[warp][0][s];
        sy += s_fold[warp][1][s];
        sz += s_fold[warp][2][s];
    }
    const float den = sx * sy * sz;

    // ---- numerator over 7^3 window ----
    float acc = 0.0f;
    #pragma unroll
    for (int u = 0; u < NITER; u++) {
        unsigned f = lane + 32u * u;
        if (f < NTRIP) {
            float w = s_fold[warp][0][ii[u]] *
                      s_fold[warp][1][jj[u]] *
                      s_fold[warp][2][kk[u]];
            acc = __fmaf_rn(w, m[u], acc);
        }
    }

    // ---- warp reduction, no block barriers anywhere ----
    #pragma unroll
    for (int o = 16; o > 0; o >>= 1)
        acc += __shfl_down_sync(0xffffffff, acc, o);
    if (lane == 0)
        out[batch + b] = acc / den;
}

extern "C" void kernel_launch(void* const* d_in, const int* in_sizes, int n_in,
                              void* d_out, int out_size) {
    const float* q       = (const float*)d_in[0];
    const float* rel     = (const float*)d_in[2];
    const float* origin  = (const float*)d_in[3];
    const float* spacing = (const float*)d_in[4];
    const float* temp    = (const float*)d_in[5];
    float* out = (float*)d_out;
    int batch = in_sizes[0] / 3;

    int blocks = (batch + QPB - 1) / QPB;
    latent_lookup_kernel<<<blocks, NTHREADS>>>(q, rel, origin, spacing, temp,
                                               out, batch);
}